// round 3
// baseline (speedup 1.0000x reference)
#include <cuda_runtime.h>
#include <math.h>
#include <stdint.h>

#define L   4096
#define H   1024
#define FF  512
#define NE  8
#define ROWS (L * 2)
#define BK  16
#define NSTG 3

// ---------------- static scratch ----------------
__device__ int      g_count[NE];
__device__ int      g_off[NE];
__device__ int      g_fill[NE];
__device__ int      g_top[L * 2];
__device__ float    g_tprob[L * 2];
__device__ int      g_perm[ROWS];
__device__ float    g_prob[ROWS];
__device__ uint32_t g_act[(size_t)ROWS * FF];          // tf32 bit patterns
__device__ uint32_t x_tf[(size_t)L * H];               // tf32 x
__device__ uint32_t w13_tf[(size_t)NE * 2 * FF * H];   // tf32 w13
__device__ uint32_t w2_tf[(size_t)NE * H * FF];        // tf32 w2

__device__ __forceinline__ uint32_t f2tf(float f) {
    uint32_t u;
    asm("cvt.rna.tf32.f32 %0, %1;" : "=r"(u) : "f"(f));
    return u;
}

__device__ __forceinline__ void mma8(float* c,
                                     uint32_t a0, uint32_t a1, uint32_t a2, uint32_t a3,
                                     uint32_t b0, uint32_t b1) {
    asm volatile(
        "mma.sync.aligned.m16n8k8.row.col.f32.tf32.tf32.f32 "
        "{%0,%1,%2,%3}, {%4,%5,%6,%7}, {%8,%9}, {%0,%1,%2,%3};"
        : "+f"(c[0]), "+f"(c[1]), "+f"(c[2]), "+f"(c[3])
        : "r"(a0), "r"(a1), "r"(a2), "r"(a3), "r"(b0), "r"(b1));
}

__device__ __forceinline__ void cpa16(uint32_t dst, const void* src) {
    asm volatile("cp.async.cg.shared.global [%0], [%1], 16;" :: "r"(dst), "l"(src));
}
#define CP_COMMIT() asm volatile("cp.async.commit_group;")
#define CP_WAIT1()  asm volatile("cp.async.wait_group 1;")

// ---------------- init / convert ----------------
__global__ void zero_kernel(float* out) {
    int i = blockIdx.x * blockDim.x + threadIdx.x;
    if (i < L * H) out[i] = 0.f;
    if (i < NE) { g_count[i] = 0; g_fill[i] = 0; }
}

__global__ void cvt_kernel(const float4* __restrict__ src, uint4* __restrict__ dst, int n4) {
    int i = blockIdx.x * blockDim.x + threadIdx.x;
    if (i < n4) {
        float4 v = src[i];
        uint4 o;
        o.x = f2tf(v.x); o.y = f2tf(v.y); o.z = f2tf(v.z); o.w = f2tf(v.w);
        dst[i] = o;
    }
}

// ---------------- router: one warp per token ----------------
__global__ void router_kernel(const float* __restrict__ x, const float* __restrict__ gw) {
    int gid  = blockIdx.x * blockDim.x + threadIdx.x;
    int tok  = gid >> 5;
    int lane = gid & 31;
    if (tok >= L) return;
    const float* xr = x + (size_t)tok * H;
    float acc[NE];
#pragma unroll
    for (int e = 0; e < NE; e++) acc[e] = 0.f;
    for (int h = lane; h < H; h += 32) {
        float xv = xr[h];
#pragma unroll
        for (int e = 0; e < NE; e++) acc[e] = fmaf(xv, gw[e * H + h], acc[e]);
    }
#pragma unroll
    for (int e = 0; e < NE; e++) {
#pragma unroll
        for (int o = 16; o > 0; o >>= 1) acc[e] += __shfl_xor_sync(0xffffffffu, acc[e], o);
    }
    if (lane == 0) {
        int i0 = 0;
#pragma unroll
        for (int e = 1; e < NE; e++) if (acc[e] > acc[i0]) i0 = e;
        int i1 = (i0 == 0) ? 1 : 0;
#pragma unroll
        for (int e = 0; e < NE; e++) if (e != i0 && acc[e] > acc[i1]) i1 = e;
        float m  = fmaxf(acc[i0], acc[i1]);
        float e0 = expf(acc[i0] - m), e1 = expf(acc[i1] - m);
        float inv = 1.f / (e0 + e1);
        g_top[tok * 2]     = i0;
        g_top[tok * 2 + 1] = i1;
        g_tprob[tok * 2]     = e0 * inv;
        g_tprob[tok * 2 + 1] = e1 * inv;
        atomicAdd(&g_count[i0], 1);
        atomicAdd(&g_count[i1], 1);
    }
}

__global__ void prefix_kernel() {
    if (threadIdx.x == 0) {
        int s = 0;
        for (int e = 0; e < NE; e++) { g_off[e] = s; s += g_count[e]; }
    }
}

__global__ void scatter_kernel() {
    int tok = blockIdx.x * blockDim.x + threadIdx.x;
    if (tok >= L) return;
#pragma unroll
    for (int j = 0; j < 2; j++) {
        int e   = g_top[tok * 2 + j];
        int pos = atomicAdd(&g_fill[e], 1);
        int r   = g_off[e] + pos;
        g_perm[r] = tok;
        g_prob[r] = g_tprob[tok * 2 + j];
    }
}

// ================= GEMM1 fused with SwiGLU (tf32 MMA, 3-stage cp.async) =================
// Tile M=128 x N=64 (gate + up). Warps 4(m) x 2(n); warp tile 32x32 per matrix.
__global__ void __launch_bounds__(256) gemm1_kernel() {
    int e   = blockIdx.z;
    int cnt = g_count[e];
    int m0  = blockIdx.y * 128;
    if (m0 >= cnt) return;
    int n0  = blockIdx.x * 64;
    int off = g_off[e];
    const uint32_t* W = w13_tf + (size_t)e * 1024 * H;

    __shared__ uint32_t As[NSTG][128][BK];
    __shared__ uint32_t Bg[NSTG][64][BK];
    __shared__ uint32_t Bu[NSTG][64][BK];

    int tid = threadIdx.x, lane = tid & 31, wid = tid >> 5;
    int wm = wid & 3, wn = wid >> 2;
    int grp = lane >> 2, thr = lane & 3;

    int rowA0 = tid >> 2, rowA1 = rowA0 + 64, kq = (tid & 3) * 4;

    int rA0 = m0 + rowA0; if (rA0 >= cnt) rA0 = 0;
    int rA1 = m0 + rowA1; if (rA1 >= cnt) rA1 = 0;
    const uint32_t* srcA0 = x_tf + (size_t)g_perm[off + rA0] * H + kq;
    const uint32_t* srcA1 = x_tf + (size_t)g_perm[off + rA1] * H + kq;
    const uint32_t* srcG  = W + (size_t)(n0 + rowA0) * H + kq;
    const uint32_t* srcU  = W + (size_t)(512 + n0 + rowA0) * H + kq;

    uint32_t sA0[NSTG], sA1[NSTG], sG[NSTG], sU[NSTG];
#pragma unroll
    for (int s = 0; s < NSTG; s++) {
        sA0[s] = (uint32_t)__cvta_generic_to_shared(&As[s][rowA0][kq]);
        sA1[s] = (uint32_t)__cvta_generic_to_shared(&As[s][rowA1][kq]);
        sG[s]  = (uint32_t)__cvta_generic_to_shared(&Bg[s][rowA0][kq]);
        sU[s]  = (uint32_t)__cvta_generic_to_shared(&Bu[s][rowA0][kq]);
    }

    float cg[2][4][4], cu[2][4][4];
#pragma unroll
    for (int i = 0; i < 2; i++)
#pragma unroll
        for (int j = 0; j < 4; j++)
#pragma unroll
            for (int k = 0; k < 4; k++) { cg[i][j][k] = 0.f; cu[i][j][k] = 0.f; }

#pragma unroll
    for (int s = 0; s < NSTG - 1; s++) {
        int k0 = s * BK;
        cpa16(sA0[s], srcA0 + k0);
        cpa16(sA1[s], srcA1 + k0);
        cpa16(sG[s],  srcG + k0);
        cpa16(sU[s],  srcU + k0);
        CP_COMMIT();
    }

    const int NIT = H / BK;
    for (int it = 0; it < NIT; it++) {
        CP_WAIT1();
        __syncthreads();
        int cur = it % NSTG;

        int kn = (it + NSTG - 1) * BK;
        if (kn < H) {
            int nst = (it + NSTG - 1) % NSTG;
            cpa16(sA0[nst], srcA0 + kn);
            cpa16(sA1[nst], srcA1 + kn);
            cpa16(sG[nst],  srcG + kn);
            cpa16(sU[nst],  srcU + kn);
        }
        CP_COMMIT();

        uint4 af[2][2];
#pragma unroll
        for (int mt = 0; mt < 2; mt++) {
            int r = wm * 32 + mt * 16 + grp;
            af[mt][0] = *(const uint4*)&As[cur][r][thr * 4];
            af[mt][1] = *(const uint4*)&As[cur][r + 8][thr * 4];
        }
        uint4 bgf[4], buf_[4];
#pragma unroll
        for (int nt = 0; nt < 4; nt++) {
            int c = wn * 32 + nt * 8 + grp;
            bgf[nt]  = *(const uint4*)&Bg[cur][c][thr * 4];
            buf_[nt] = *(const uint4*)&Bu[cur][c][thr * 4];
        }
#pragma unroll
        for (int s = 0; s < 2; s++) {
#pragma unroll
            for (int mt = 0; mt < 2; mt++) {
                const uint32_t* a0p = (const uint32_t*)&af[mt][0];
                const uint32_t* a1p = (const uint32_t*)&af[mt][1];
                uint32_t A0 = a0p[s], A1 = a1p[s], A2 = a0p[2 + s], A3 = a1p[2 + s];
#pragma unroll
                for (int nt = 0; nt < 4; nt++) {
                    const uint32_t* bp = (const uint32_t*)&bgf[nt];
                    mma8(cg[mt][nt], A0, A1, A2, A3, bp[s], bp[2 + s]);
                    const uint32_t* up = (const uint32_t*)&buf_[nt];
                    mma8(cu[mt][nt], A0, A1, A2, A3, up[s], up[2 + s]);
                }
            }
        }
    }

    // epilogue: act = silu(g)*u  (stored pre-converted to tf32)
#pragma unroll
    for (int mt = 0; mt < 2; mt++) {
#pragma unroll
        for (int h2 = 0; h2 < 2; h2++) {
            int m = m0 + wm * 32 + mt * 16 + grp + h2 * 8;
            if (m < cnt) {
                size_t base = (size_t)(off + m) * FF;
#pragma unroll
                for (int nt = 0; nt < 4; nt++) {
                    int f = n0 + wn * 32 + nt * 8 + thr * 2;
                    float g0 = cg[mt][nt][h2 * 2 + 0], g1 = cg[mt][nt][h2 * 2 + 1];
                    float u0 = cu[mt][nt][h2 * 2 + 0], u1 = cu[mt][nt][h2 * 2 + 1];
                    float a0 = (g0 / (1.f + expf(-g0))) * u0;
                    float a1 = (g1 / (1.f + expf(-g1))) * u1;
                    uint2 o; o.x = f2tf(a0); o.y = f2tf(a1);
                    *(uint2*)&g_act[base + f] = o;
                }
            }
        }
    }
}

// ================= GEMM2 + weighted atomic combine (tf32 MMA, 3-stage cp.async) =================
// Tile M=128 x N=128. Warps 4(m) x 2(n); warp tile 32x64.
__global__ void __launch_bounds__(256) gemm2_kernel(float* __restrict__ out) {
    int e   = blockIdx.z;
    int cnt = g_count[e];
    int m0  = blockIdx.y * 128;
    if (m0 >= cnt) return;
    int n0  = blockIdx.x * 128;
    int off = g_off[e];
    const uint32_t* W = w2_tf + (size_t)e * H * FF;

    __shared__ uint32_t As[NSTG][128][BK];
    __shared__ uint32_t Bs[NSTG][128][BK];

    int tid = threadIdx.x, lane = tid & 31, wid = tid >> 5;
    int wm = wid & 3, wn = wid >> 2;
    int grp = lane >> 2, thr = lane & 3;

    int rowA0 = tid >> 2, rowA1 = rowA0 + 64, kq = (tid & 3) * 4;

    int rA0 = m0 + rowA0; if (rA0 >= cnt) rA0 = 0;
    int rA1 = m0 + rowA1; if (rA1 >= cnt) rA1 = 0;
    const uint32_t* srcA0 = g_act + (size_t)(off + rA0) * FF + kq;
    const uint32_t* srcA1 = g_act + (size_t)(off + rA1) * FF + kq;
    const uint32_t* srcB0 = W + (size_t)(n0 + rowA0) * FF + kq;
    const uint32_t* srcB1 = W + (size_t)(n0 + rowA1) * FF + kq;

    uint32_t sA0[NSTG], sA1[NSTG], sB0[NSTG], sB1[NSTG];
#pragma unroll
    for (int s = 0; s < NSTG; s++) {
        sA0[s] = (uint32_t)__cvta_generic_to_shared(&As[s][rowA0][kq]);
        sA1[s] = (uint32_t)__cvta_generic_to_shared(&As[s][rowA1][kq]);
        sB0[s] = (uint32_t)__cvta_generic_to_shared(&Bs[s][rowA0][kq]);
        sB1[s] = (uint32_t)__cvta_generic_to_shared(&Bs[s][rowA1][kq]);
    }

    float acc[2][8][4];
#pragma unroll
    for (int i = 0; i < 2; i++)
#pragma unroll
        for (int j = 0; j < 8; j++)
#pragma unroll
            for (int k = 0; k < 4; k++) acc[i][j][k] = 0.f;

#pragma unroll
    for (int s = 0; s < NSTG - 1; s++) {
        int k0 = s * BK;
        cpa16(sA0[s], srcA0 + k0);
        cpa16(sA1[s], srcA1 + k0);
        cpa16(sB0[s], srcB0 + k0);
        cpa16(sB1[s], srcB1 + k0);
        CP_COMMIT();
    }

    const int NIT = FF / BK;
    for (int it = 0; it < NIT; it++) {
        CP_WAIT1();
        __syncthreads();
        int cur = it % NSTG;

        int kn = (it + NSTG - 1) * BK;
        if (kn < FF) {
            int nst = (it + NSTG - 1) % NSTG;
            cpa16(sA0[nst], srcA0 + kn);
            cpa16(sA1[nst], srcA1 + kn);
            cpa16(sB0[nst], srcB0 + kn);
            cpa16(sB1[nst], srcB1 + kn);
        }
        CP_COMMIT();

        uint4 af[2][2];
#pragma unroll
        for (int mt = 0; mt < 2; mt++) {
            int r = wm * 32 + mt * 16 + grp;
            af[mt][0] = *(const uint4*)&As[cur][r][thr * 4];
            af[mt][1] = *(const uint4*)&As[cur][r + 8][thr * 4];
        }
        uint4 bf[8];
#pragma unroll
        for (int nt = 0; nt < 8; nt++) {
            int c = wn * 64 + nt * 8 + grp;
            bf[nt] = *(const uint4*)&Bs[cur][c][thr * 4];
        }
#pragma unroll
        for (int s = 0; s < 2; s++) {
#pragma unroll
            for (int mt = 0; mt < 2; mt++) {
                const uint32_t* a0p = (const uint32_t*)&af[mt][0];
                const uint32_t* a1p = (const uint32_t*)&af[mt][1];
                uint32_t A0 = a0p[s], A1 = a1p[s], A2 = a0p[2 + s], A3 = a1p[2 + s];
#pragma unroll
                for (int nt = 0; nt < 8; nt++) {
                    const uint32_t* bp = (const uint32_t*)&bf[nt];
                    mma8(acc[mt][nt], A0, A1, A2, A3, bp[s], bp[2 + s]);
                }
            }
        }
    }

    // weighted combine: exactly 2 expert contributions per token -> atomicAdd
#pragma unroll
    for (int mt = 0; mt < 2; mt++) {
#pragma unroll
        for (int h2 = 0; h2 < 2; h2++) {
            int m = m0 + wm * 32 + mt * 16 + grp + h2 * 8;
            if (m < cnt) {
                int   r   = off + m;
                int   tok = g_perm[r];
                float p   = g_prob[r];
                float* o  = out + (size_t)tok * H;
#pragma unroll
                for (int nt = 0; nt < 8; nt++) {
                    int n = n0 + wn * 64 + nt * 8 + thr * 2;
                    atomicAdd(&o[n],     p * acc[mt][nt][h2 * 2 + 0]);
                    atomicAdd(&o[n + 1], p * acc[mt][nt][h2 * 2 + 1]);
                }
            }
        }
    }
}

// ---------------- launch ----------------
extern "C" void kernel_launch(void* const* d_in, const int* in_sizes, int n_in,
                              void* d_out, int out_size) {
    const float* x   = (const float*)d_in[0];
    const float* gw  = (const float*)d_in[1];
    const float* w13 = (const float*)d_in[2];
    const float* w2  = (const float*)d_in[3];
    float* out = (float*)d_out;

    uint32_t* xtf;  cudaGetSymbolAddress((void**)&xtf,  x_tf);
    uint32_t* w13t; cudaGetSymbolAddress((void**)&w13t, w13_tf);
    uint32_t* w2t;  cudaGetSymbolAddress((void**)&w2t,  w2_tf);

    zero_kernel<<<(L * H + 255) / 256, 256>>>(out);
    cvt_kernel<<<(L * H / 4 + 255) / 256, 256>>>((const float4*)x, (uint4*)xtf, L * H / 4);
    cvt_kernel<<<(NE * 2 * FF * H / 4 + 255) / 256, 256>>>((const float4*)w13, (uint4*)w13t, NE * 2 * FF * H / 4);
    cvt_kernel<<<(NE * H * FF / 4 + 255) / 256, 256>>>((const float4*)w2, (uint4*)w2t, NE * H * FF / 4);
    router_kernel<<<(L * 32 + 255) / 256, 256>>>(x, gw);
    prefix_kernel<<<1, 32>>>();
    scatter_kernel<<<(L + 255) / 256, 256>>>();
    gemm1_kernel<<<dim3(512 / 64, ROWS / 128, NE), 256>>>();
    gemm2_kernel<<<dim3(H / 128, ROWS / 128, NE), 256>>>(out);
}

// round 5
// speedup vs baseline: 1.6092x; 1.6092x over previous
#include <cuda_runtime.h>
#include <cuda_fp16.h>
#include <math.h>
#include <stdint.h>

#define L   4096
#define H   1024
#define FF  512
#define NE  8
#define ROWS (L * 2)
#define BK  32
#define NSTG 3
#define ROWB 80                       // padded smem row: 32 halves data + 8 pad = 80B
#define STG_SZ (256 * ROWB)           // 128 A rows + 128 B rows = 20480B
#define SMEM_BYTES (NSTG * STG_SZ)    // 61440

// ---------------- static scratch ----------------
__device__ int    g_count[NE];
__device__ int    g_off[NE];
__device__ int    g_fill[NE];
__device__ int    g_top[L * 2];
__device__ float  g_tprob[L * 2];
__device__ int    g_perm[ROWS];
__device__ float  g_prob[ROWS];
__device__ __half g_act[(size_t)ROWS * FF];
__device__ __half x_h[(size_t)L * H];
__device__ __half w13_h[(size_t)NE * 1024 * H];
__device__ __half w2_h[(size_t)NE * H * FF];

// ---------------- helpers ----------------
__device__ __forceinline__ uint32_t smem_u32(const void* p) {
    uint32_t a;
    asm("{ .reg .u64 t; cvta.to.shared.u64 t, %1; cvt.u32.u64 %0, t; }" : "=r"(a) : "l"(p));
    return a;
}
__device__ __forceinline__ void ldsm4(uint32_t* r, uint32_t addr) {
    asm volatile("ldmatrix.sync.aligned.m8n8.x4.shared.b16 {%0,%1,%2,%3}, [%4];"
                 : "=r"(r[0]), "=r"(r[1]), "=r"(r[2]), "=r"(r[3]) : "r"(addr));
}
__device__ __forceinline__ void mma16(float* c, const uint32_t* a, uint32_t b0, uint32_t b1) {
    asm volatile(
        "mma.sync.aligned.m16n8k16.row.col.f32.f16.f16.f32 "
        "{%0,%1,%2,%3},{%4,%5,%6,%7},{%8,%9},{%0,%1,%2,%3};"
        : "+f"(c[0]), "+f"(c[1]), "+f"(c[2]), "+f"(c[3])
        : "r"(a[0]), "r"(a[1]), "r"(a[2]), "r"(a[3]), "r"(b0), "r"(b1));
}
__device__ __forceinline__ void cpa16(uint32_t dst, const void* src) {
    asm volatile("cp.async.cg.shared.global [%0], [%1], 16;" :: "r"(dst), "l"(src));
}
#define CP_COMMIT() asm volatile("cp.async.commit_group;")
#define CP_WAIT(N)  asm volatile("cp.async.wait_group %0;" :: "n"(N))

// ---------------- small kernels ----------------
__global__ void zero_kernel(float* out) {
    int i = blockIdx.x * blockDim.x + threadIdx.x;
    if (i < L * H) out[i] = 0.f;
    if (i < NE) { g_count[i] = 0; g_fill[i] = 0; }
}

__global__ void cvt_kernel(const float4* __restrict__ src, uint2* __restrict__ dst, int n4) {
    int stride = gridDim.x * blockDim.x;
    for (int i = blockIdx.x * blockDim.x + threadIdx.x; i < n4; i += stride) {
        float4 v = src[i];
        __half2 h0 = __floats2half2_rn(v.x, v.y);
        __half2 h1 = __floats2half2_rn(v.z, v.w);
        uint2 o;
        o.x = *reinterpret_cast<uint32_t*>(&h0);
        o.y = *reinterpret_cast<uint32_t*>(&h1);
        dst[i] = o;
    }
}

__global__ void router_kernel(const float* __restrict__ x, const float* __restrict__ gw) {
    int gid  = blockIdx.x * blockDim.x + threadIdx.x;
    int tok  = gid >> 5;
    int lane = gid & 31;
    if (tok >= L) return;
    const float* xr = x + (size_t)tok * H;
    float acc[NE];
#pragma unroll
    for (int e = 0; e < NE; e++) acc[e] = 0.f;
    for (int h = lane; h < H; h += 32) {
        float xv = xr[h];
#pragma unroll
        for (int e = 0; e < NE; e++) acc[e] = fmaf(xv, gw[e * H + h], acc[e]);
    }
#pragma unroll
    for (int e = 0; e < NE; e++) {
#pragma unroll
        for (int o = 16; o > 0; o >>= 1) acc[e] += __shfl_xor_sync(0xffffffffu, acc[e], o);
    }
    if (lane == 0) {
        int i0 = 0;
#pragma unroll
        for (int e = 1; e < NE; e++) if (acc[e] > acc[i0]) i0 = e;
        int i1 = (i0 == 0) ? 1 : 0;
#pragma unroll
        for (int e = 0; e < NE; e++) if (e != i0 && acc[e] > acc[i1]) i1 = e;
        float m  = fmaxf(acc[i0], acc[i1]);
        float e0 = expf(acc[i0] - m), e1 = expf(acc[i1] - m);
        float inv = 1.f / (e0 + e1);
        g_top[tok * 2] = i0; g_top[tok * 2 + 1] = i1;
        g_tprob[tok * 2] = e0 * inv; g_tprob[tok * 2 + 1] = e1 * inv;
        atomicAdd(&g_count[i0], 1);
        atomicAdd(&g_count[i1], 1);
    }
}

__global__ void prefix_kernel() {
    if (threadIdx.x == 0) {
        int s = 0;
        for (int e = 0; e < NE; e++) { g_off[e] = s; s += g_count[e]; }
    }
}

__global__ void scatter_kernel() {
    int tok = blockIdx.x * blockDim.x + threadIdx.x;
    if (tok >= L) return;
#pragma unroll
    for (int j = 0; j < 2; j++) {
        int e   = g_top[tok * 2 + j];
        int pos = atomicAdd(&g_fill[e], 1);
        int r   = g_off[e] + pos;
        g_perm[r] = tok;
        g_prob[r] = g_tprob[tok * 2 + j];
    }
}

// ================= GEMM1 fused SwiGLU: fp16 mma.sync, M128 x N64(g)+64(u), K=1024 =================
__global__ void __launch_bounds__(256) gemm1_kernel() {
    int e   = blockIdx.z;
    int cnt = g_count[e];
    int m0  = blockIdx.y * 128;
    if (m0 >= cnt) return;
    int n0  = blockIdx.x * 64;
    int off = g_off[e];

    extern __shared__ char smem[];
    uint32_t sb = smem_u32(smem);

    int tid = threadIdx.x, lane = tid & 31, wid = tid >> 5;
    int wm = wid & 3, wn = wid >> 2;
    int grp = lane >> 2, thr = lane & 3;

    // loader: thread t owns one 32-half row segment per stage
    const __half* src;
    if (tid < 128) {
        int rA = m0 + tid; if (rA >= cnt) rA = m0;
        src = x_h + (size_t)g_perm[off + rA] * H;
    } else {
        int rb = tid - 128;
        int nrow = (rb < 64) ? (n0 + rb) : (512 + n0 + (rb - 64));
        src = w13_h + (size_t)e * 1024 * H + (size_t)nrow * H;
    }
    uint32_t dstrow = sb + (uint32_t)tid * ROWB;

#define G_FILL(S, K0)                                             \
    {                                                             \
        uint32_t base = dstrow + (S) * STG_SZ;                    \
        _Pragma("unroll")                                         \
        for (int j = 0; j < 4; j++)                               \
            cpa16(base + j * 16, src + (K0) + j * 8);             \
    }

    // fragment lane offsets (bytes)
    uint32_t aoff = (uint32_t)((lane & 15) * ROWB + ((lane >> 4) << 3) * 2);
    uint32_t boff = (uint32_t)(((((lane >> 4) << 3) + (lane & 7)) * ROWB) + ((((lane >> 3) & 1) << 3) * 2));
    const uint32_t BREG = 128 * ROWB;

    float cg[2][4][4], cu[2][4][4];
#pragma unroll
    for (int i = 0; i < 2; i++)
#pragma unroll
        for (int j = 0; j < 4; j++)
#pragma unroll
            for (int k = 0; k < 4; k++) { cg[i][j][k] = 0.f; cu[i][j][k] = 0.f; }

    G_FILL(0, 0); CP_COMMIT();
    G_FILL(1, BK); CP_COMMIT();

    const int NIT = H / BK;  // 32
    for (int it = 0; it < NIT; it++) {
        CP_WAIT(1);
        __syncthreads();
        int cur = it % NSTG;
        int kn = it + NSTG - 1;
        if (kn < NIT) { G_FILL(kn % NSTG, kn * BK); }
        CP_COMMIT();

        uint32_t sc = sb + cur * STG_SZ;
#pragma unroll
        for (int ks = 0; ks < 2; ks++) {
            uint32_t a[2][4];
#pragma unroll
            for (int mt = 0; mt < 2; mt++)
                ldsm4(a[mt], sc + (uint32_t)((wm * 32 + mt * 16) * ROWB + ks * 32) + aoff);
            uint32_t bg[2][4], bu[2][4];
#pragma unroll
            for (int nt16 = 0; nt16 < 2; nt16++) {
                ldsm4(bg[nt16], sc + BREG + (uint32_t)((wn * 32 + nt16 * 16) * ROWB + ks * 32) + boff);
                ldsm4(bu[nt16], sc + BREG + (uint32_t)(((64 + wn * 32 + nt16 * 16)) * ROWB + ks * 32) + boff);
            }
#pragma unroll
            for (int mt = 0; mt < 2; mt++) {
#pragma unroll
                for (int nt = 0; nt < 4; nt++) {
                    mma16(cg[mt][nt], a[mt], bg[nt >> 1][(nt & 1) * 2], bg[nt >> 1][(nt & 1) * 2 + 1]);
                    mma16(cu[mt][nt], a[mt], bu[nt >> 1][(nt & 1) * 2], bu[nt >> 1][(nt & 1) * 2 + 1]);
                }
            }
        }
    }

    // epilogue: act = silu(g)*u -> half2 stores
#pragma unroll
    for (int mt = 0; mt < 2; mt++) {
#pragma unroll
        for (int h2 = 0; h2 < 2; h2++) {
            int m = m0 + wm * 32 + mt * 16 + grp + h2 * 8;
            if (m < cnt) {
                size_t base = (size_t)(off + m) * FF;
#pragma unroll
                for (int nt = 0; nt < 4; nt++) {
                    int f = n0 + wn * 32 + nt * 8 + thr * 2;
                    float g0 = cg[mt][nt][h2 * 2 + 0], g1 = cg[mt][nt][h2 * 2 + 1];
                    float u0 = cu[mt][nt][h2 * 2 + 0], u1 = cu[mt][nt][h2 * 2 + 1];
                    float a0 = (g0 / (1.f + expf(-g0))) * u0;
                    float a1 = (g1 / (1.f + expf(-g1))) * u1;
                    *(__half2*)&g_act[base + f] = __floats2half2_rn(a0, a1);
                }
            }
        }
    }
}

// ================= GEMM2 + weighted combine: fp16 mma.sync, M128 x N128, K=512 =================
__global__ void __launch_bounds__(256) gemm2_kernel(float* __restrict__ out) {
    int e   = blockIdx.z;
    int cnt = g_count[e];
    int m0  = blockIdx.y * 128;
    if (m0 >= cnt) return;
    int n0  = blockIdx.x * 128;
    int off = g_off[e];

    extern __shared__ char smem[];
    uint32_t sb = smem_u32(smem);

    int tid = threadIdx.x, lane = tid & 31, wid = tid >> 5;
    int wm = wid & 3, wn = wid >> 2;
    int grp = lane >> 2, thr = lane & 3;

    const __half* src;
    if (tid < 128) {
        int rA = m0 + tid; if (rA >= cnt) rA = m0;
        src = g_act + (size_t)(off + rA) * FF;
    } else {
        src = w2_h + (size_t)e * H * FF + (size_t)(n0 + tid - 128) * FF;
    }
    uint32_t dstrow = sb + (uint32_t)tid * ROWB;

    uint32_t aoff = (uint32_t)((lane & 15) * ROWB + ((lane >> 4) << 3) * 2);
    uint32_t boff = (uint32_t)(((((lane >> 4) << 3) + (lane & 7)) * ROWB) + ((((lane >> 3) & 1) << 3) * 2));
    const uint32_t BREG = 128 * ROWB;

    float acc[2][8][4];
#pragma unroll
    for (int i = 0; i < 2; i++)
#pragma unroll
        for (int j = 0; j < 8; j++)
#pragma unroll
            for (int k = 0; k < 4; k++) acc[i][j][k] = 0.f;

    G_FILL(0, 0); CP_COMMIT();
    G_FILL(1, BK); CP_COMMIT();

    const int NIT = FF / BK;  // 16
    for (int it = 0; it < NIT; it++) {
        CP_WAIT(1);
        __syncthreads();
        int cur = it % NSTG;
        int kn = it + NSTG - 1;
        if (kn < NIT) { G_FILL(kn % NSTG, kn * BK); }
        CP_COMMIT();

        uint32_t sc = sb + cur * STG_SZ;
#pragma unroll
        for (int ks = 0; ks < 2; ks++) {
            uint32_t a[2][4];
#pragma unroll
            for (int mt = 0; mt < 2; mt++)
                ldsm4(a[mt], sc + (uint32_t)((wm * 32 + mt * 16) * ROWB + ks * 32) + aoff);
            uint32_t b[4][4];
#pragma unroll
            for (int nt16 = 0; nt16 < 4; nt16++)
                ldsm4(b[nt16], sc + BREG + (uint32_t)((wn * 64 + nt16 * 16) * ROWB + ks * 32) + boff);
#pragma unroll
            for (int mt = 0; mt < 2; mt++) {
#pragma unroll
                for (int nt = 0; nt < 8; nt++) {
                    mma16(acc[mt][nt], a[mt], b[nt >> 1][(nt & 1) * 2], b[nt >> 1][(nt & 1) * 2 + 1]);
                }
            }
        }
    }

    // weighted combine: exactly 2 contributions per token element -> atomicAdd
#pragma unroll
    for (int mt = 0; mt < 2; mt++) {
#pragma unroll
        for (int h2 = 0; h2 < 2; h2++) {
            int m = m0 + wm * 32 + mt * 16 + grp + h2 * 8;
            if (m < cnt) {
                int   r   = off + m;
                int   tok = g_perm[r];
                float p   = g_prob[r];
                float* o  = out + (size_t)tok * H;
#pragma unroll
                for (int nt = 0; nt < 8; nt++) {
                    int n = n0 + wn * 64 + nt * 8 + thr * 2;
                    atomicAdd(&o[n],     p * acc[mt][nt][h2 * 2 + 0]);
                    atomicAdd(&o[n + 1], p * acc[mt][nt][h2 * 2 + 1]);
                }
            }
        }
    }
}

// ---------------- launch ----------------
extern "C" void kernel_launch(void* const* d_in, const int* in_sizes, int n_in,
                              void* d_out, int out_size) {
    const float* x   = (const float*)d_in[0];
    const float* gw  = (const float*)d_in[1];
    const float* w13 = (const float*)d_in[2];
    const float* w2  = (const float*)d_in[3];
    float* out = (float*)d_out;

    __half* xh;  cudaGetSymbolAddress((void**)&xh,  x_h);
    __half* w13h; cudaGetSymbolAddress((void**)&w13h, w13_h);
    __half* w2h;  cudaGetSymbolAddress((void**)&w2h,  w2_h);

    static bool attr_done = false;
    if (!attr_done) {
        cudaFuncSetAttribute(gemm1_kernel, cudaFuncAttributeMaxDynamicSharedMemorySize, SMEM_BYTES);
        cudaFuncSetAttribute(gemm2_kernel, cudaFuncAttributeMaxDynamicSharedMemorySize, SMEM_BYTES);
        attr_done = true;
    }

    zero_kernel<<<(L * H + 255) / 256, 256>>>(out);
    cvt_kernel<<<1024, 256>>>((const float4*)x,   (uint2*)xh,   L * H / 4);
    cvt_kernel<<<2048, 256>>>((const float4*)w13, (uint2*)w13h, NE * 2 * FF * H / 4);
    cvt_kernel<<<2048, 256>>>((const float4*)w2,  (uint2*)w2h,  NE * H * FF / 4);
    router_kernel<<<(L * 32 + 255) / 256, 256>>>(x, gw);
    prefix_kernel<<<1, 32>>>();
    scatter_kernel<<<(L + 255) / 256, 256>>>();
    gemm1_kernel<<<dim3(FF / 64, ROWS / 128, NE), 256, SMEM_BYTES>>>();
    gemm2_kernel<<<dim3(H / 128, ROWS / 128, NE), 256, SMEM_BYTES>>>(out);
}

// round 6
// speedup vs baseline: 2.3006x; 1.4296x over previous
#include <cuda_runtime.h>
#include <cuda_fp16.h>
#include <math.h>
#include <stdint.h>

#define L   4096
#define H   1024
#define FF  512
#define NE  8
#define ROWS (L * 2)
#define BK  32
#define NSTG 3
#define ROWB 80                        // 32 halves data (64B) + 16B pad
#define STG_SZ (256 * ROWB)            // 128 A rows + 128 B rows = 20480B
#define SMEM_BYTES (NSTG * STG_SZ)     // 61440
#define BREG (128 * ROWB)

// ---------------- static scratch ----------------
__device__ int    g_count[NE];
__device__ int    g_off[NE];
__device__ int    g_fill[NE];
__device__ int    g_top[L * 2];
__device__ float  g_tprob[L * 2];
__device__ int    g_perm[ROWS];
__device__ float  g_prob[ROWS];
__device__ __half g_act[(size_t)ROWS * FF];
__device__ __half x_h[(size_t)L * H];
__device__ __half w13_h[(size_t)NE * 1024 * H];
__device__ __half w2_h[(size_t)NE * H * FF];

// ---------------- helpers ----------------
__device__ __forceinline__ uint32_t smem_u32(const void* p) {
    uint32_t a;
    asm("{ .reg .u64 t; cvta.to.shared.u64 t, %1; cvt.u32.u64 %0, t; }" : "=r"(a) : "l"(p));
    return a;
}
__device__ __forceinline__ void ldsm4(uint32_t* r, uint32_t addr) {
    asm volatile("ldmatrix.sync.aligned.m8n8.x4.shared.b16 {%0,%1,%2,%3}, [%4];"
                 : "=r"(r[0]), "=r"(r[1]), "=r"(r[2]), "=r"(r[3]) : "r"(addr));
}
__device__ __forceinline__ void mma16(float* c, const uint32_t* a, uint32_t b0, uint32_t b1) {
    asm volatile(
        "mma.sync.aligned.m16n8k16.row.col.f32.f16.f16.f32 "
        "{%0,%1,%2,%3},{%4,%5,%6,%7},{%8,%9},{%0,%1,%2,%3};"
        : "+f"(c[0]), "+f"(c[1]), "+f"(c[2]), "+f"(c[3])
        : "r"(a[0]), "r"(a[1]), "r"(a[2]), "r"(a[3]), "r"(b0), "r"(b1));
}
__device__ __forceinline__ void cpa16(uint32_t dst, const void* src) {
    asm volatile("cp.async.cg.shared.global [%0], [%1], 16;" :: "r"(dst), "l"(src));
}
#define CP_COMMIT() asm volatile("cp.async.commit_group;")
#define CP_WAIT(N)  asm volatile("cp.async.wait_group %0;" :: "n"(N))

// ---------------- prep: zero out + convert x/w13/w2 to fp16 ----------------
#define NX4   (L * H / 4)
#define NW134 (NE * 2 * FF * H / 4)
#define NW24  (NE * H * FF / 4)
__global__ void prep_kernel(float* __restrict__ out,
                            const float4* __restrict__ x,
                            const float4* __restrict__ w13,
                            const float4* __restrict__ w2,
                            uint2* __restrict__ xh, uint2* __restrict__ w13h,
                            uint2* __restrict__ w2h) {
    int stride = gridDim.x * blockDim.x;
    int tid0 = blockIdx.x * blockDim.x + threadIdx.x;
    if (tid0 < NE) { g_count[tid0] = 0; g_fill[tid0] = 0; }
    const int TOT = NX4 + NW134 + NW24;
    for (int i = tid0; i < TOT; i += stride) {
        float4 v;
        uint2* d;
        if (i < NX4) {
            *(float4*)&out[(size_t)i * 4] = make_float4(0.f, 0.f, 0.f, 0.f);
            v = x[i]; d = xh + i;
        } else if (i < NX4 + NW134) {
            v = w13[i - NX4]; d = w13h + (i - NX4);
        } else {
            v = w2[i - NX4 - NW134]; d = w2h + (i - NX4 - NW134);
        }
        __half2 h0 = __floats2half2_rn(v.x, v.y);
        __half2 h1 = __floats2half2_rn(v.z, v.w);
        uint2 o;
        o.x = *reinterpret_cast<uint32_t*>(&h0);
        o.y = *reinterpret_cast<uint32_t*>(&h1);
        *d = o;
    }
}

// ---------------- router ----------------
__global__ void router_kernel(const float* __restrict__ x, const float* __restrict__ gw) {
    int gid  = blockIdx.x * blockDim.x + threadIdx.x;
    int tok  = gid >> 5;
    int lane = gid & 31;
    if (tok >= L) return;
    const float* xr = x + (size_t)tok * H;
    float acc[NE];
#pragma unroll
    for (int e = 0; e < NE; e++) acc[e] = 0.f;
    for (int h = lane; h < H; h += 32) {
        float xv = xr[h];
#pragma unroll
        for (int e = 0; e < NE; e++) acc[e] = fmaf(xv, gw[e * H + h], acc[e]);
    }
#pragma unroll
    for (int e = 0; e < NE; e++) {
#pragma unroll
        for (int o = 16; o > 0; o >>= 1) acc[e] += __shfl_xor_sync(0xffffffffu, acc[e], o);
    }
    if (lane == 0) {
        int i0 = 0;
#pragma unroll
        for (int e = 1; e < NE; e++) if (acc[e] > acc[i0]) i0 = e;
        int i1 = (i0 == 0) ? 1 : 0;
#pragma unroll
        for (int e = 0; e < NE; e++) if (e != i0 && acc[e] > acc[i1]) i1 = e;
        float m  = fmaxf(acc[i0], acc[i1]);
        float e0 = expf(acc[i0] - m), e1 = expf(acc[i1] - m);
        float inv = 1.f / (e0 + e1);
        g_top[tok * 2] = i0; g_top[tok * 2 + 1] = i1;
        g_tprob[tok * 2] = e0 * inv; g_tprob[tok * 2 + 1] = e1 * inv;
        atomicAdd(&g_count[i0], 1);
        atomicAdd(&g_count[i1], 1);
    }
}

__global__ void prefix_kernel() {
    if (threadIdx.x == 0) {
        int s = 0;
        for (int e = 0; e < NE; e++) { g_off[e] = s; s += g_count[e]; }
    }
}

__global__ void scatter_kernel() {
    int tok = blockIdx.x * blockDim.x + threadIdx.x;
    if (tok >= L) return;
#pragma unroll
    for (int j = 0; j < 2; j++) {
        int e   = g_top[tok * 2 + j];
        int pos = atomicAdd(&g_fill[e], 1);
        int r   = g_off[e] + pos;
        g_perm[r] = tok;
        g_prob[r] = g_tprob[tok * 2 + j];
    }
}

// ================= GEMM1 fused SwiGLU: 128 thr, warp tile 64x(32g+32u), K=1024 =================
__global__ void __launch_bounds__(128) gemm1_kernel() {
    int e   = blockIdx.z;
    int cnt = g_count[e];
    int m0  = blockIdx.y * 128;
    if (m0 >= cnt) return;
    int n0  = blockIdx.x * 64;
    int off = g_off[e];

    extern __shared__ char smem[];
    uint32_t sb = smem_u32(smem);

    int tid = threadIdx.x, lane = tid & 31, wid = tid >> 5;
    int wm = wid & 1, wn = wid >> 1;
    int grp = lane >> 2, thr = lane & 3;

    // loader: 256 rows x 4 segs = 1024 segs; thread t -> rows (t>>2)+32i, seg j=t&3
    const __half* srcp[8];
    uint32_t dstoff[8];
    {
        int j = tid & 3, r0 = tid >> 2;
        const __half* W = w13_h + (size_t)e * 1024 * H;
#pragma unroll
        for (int i = 0; i < 8; i++) {
            int row = r0 + 32 * i;
            const __half* s;
            if (row < 128) {
                int rA = m0 + row; if (rA >= cnt) rA = m0;
                s = x_h + (size_t)g_perm[off + rA] * H;
            } else if (row < 192) {
                s = W + (size_t)(n0 + row - 128) * H;
            } else {
                s = W + (size_t)(512 + n0 + row - 192) * H;
            }
            srcp[i] = s + j * 8;
            dstoff[i] = (uint32_t)(row * ROWB + j * 16);
        }
    }

#define G_FILL(S, K0)                                          \
    {                                                          \
        uint32_t bb = sb + (S) * STG_SZ;                       \
        _Pragma("unroll")                                      \
        for (int i = 0; i < 8; i++)                            \
            cpa16(bb + dstoff[i], srcp[i] + (K0));             \
    }

    uint32_t aoff = (uint32_t)((lane & 15) * ROWB + (lane >> 4) * 16);
    uint32_t boff = (uint32_t)((((lane >> 4) * 8 + (lane & 7)) * ROWB) + (((lane >> 3) & 1) * 16));

    float cg[4][4][4], cu[4][4][4];
#pragma unroll
    for (int i = 0; i < 4; i++)
#pragma unroll
        for (int j = 0; j < 4; j++)
#pragma unroll
            for (int k = 0; k < 4; k++) { cg[i][j][k] = 0.f; cu[i][j][k] = 0.f; }

    G_FILL(0, 0); CP_COMMIT();
    G_FILL(1, BK); CP_COMMIT();

    const int NIT = H / BK;  // 32
    for (int it = 0; it < NIT; it++) {
        CP_WAIT(1);
        __syncthreads();
        int cur = it % NSTG;
        int kn = it + NSTG - 1;
        if (kn < NIT) { G_FILL(kn % NSTG, kn * BK); }
        CP_COMMIT();

        uint32_t sc = sb + cur * STG_SZ;
#pragma unroll
        for (int ks = 0; ks < 2; ks++) {
            uint32_t a[4][4];
#pragma unroll
            for (int mt = 0; mt < 4; mt++)
                ldsm4(a[mt], sc + (uint32_t)((wm * 64 + mt * 16) * ROWB + ks * 32) + aoff);
            uint32_t bg[2][4], bu[2][4];
#pragma unroll
            for (int nt16 = 0; nt16 < 2; nt16++) {
                ldsm4(bg[nt16], sc + BREG + (uint32_t)((wn * 32 + nt16 * 16) * ROWB + ks * 32) + boff);
                ldsm4(bu[nt16], sc + BREG + (uint32_t)((64 + wn * 32 + nt16 * 16) * ROWB + ks * 32) + boff);
            }
#pragma unroll
            for (int mt = 0; mt < 4; mt++) {
#pragma unroll
                for (int nt = 0; nt < 4; nt++) {
                    mma16(cg[mt][nt], a[mt], bg[nt >> 1][(nt & 1) * 2], bg[nt >> 1][(nt & 1) * 2 + 1]);
                    mma16(cu[mt][nt], a[mt], bu[nt >> 1][(nt & 1) * 2], bu[nt >> 1][(nt & 1) * 2 + 1]);
                }
            }
        }
    }

    // epilogue: act = silu(g)*u
#pragma unroll
    for (int mt = 0; mt < 4; mt++) {
#pragma unroll
        for (int h2 = 0; h2 < 2; h2++) {
            int m = m0 + wm * 64 + mt * 16 + grp + h2 * 8;
            if (m < cnt) {
                size_t base = (size_t)(off + m) * FF;
#pragma unroll
                for (int nt = 0; nt < 4; nt++) {
                    int f = n0 + wn * 32 + nt * 8 + thr * 2;
                    float g0 = cg[mt][nt][h2 * 2 + 0], g1 = cg[mt][nt][h2 * 2 + 1];
                    float u0 = cu[mt][nt][h2 * 2 + 0], u1 = cu[mt][nt][h2 * 2 + 1];
                    float a0 = (g0 / (1.f + expf(-g0))) * u0;
                    float a1 = (g1 / (1.f + expf(-g1))) * u1;
                    *(__half2*)&g_act[base + f] = __floats2half2_rn(a0, a1);
                }
            }
        }
    }
}

// ================= GEMM2 + weighted combine: 128 thr, warp tile 64x64, K=512 =================
__global__ void __launch_bounds__(128) gemm2_kernel(float* __restrict__ out) {
    int e   = blockIdx.z;
    int cnt = g_count[e];
    int m0  = blockIdx.y * 128;
    if (m0 >= cnt) return;
    int n0  = blockIdx.x * 128;
    int off = g_off[e];

    extern __shared__ char smem[];
    uint32_t sb = smem_u32(smem);

    int tid = threadIdx.x, lane = tid & 31, wid = tid >> 5;
    int wm = wid & 1, wn = wid >> 1;
    int grp = lane >> 2, thr = lane & 3;

    const __half* srcp[8];
    uint32_t dstoff[8];
    {
        int j = tid & 3, r0 = tid >> 2;
        const __half* W = w2_h + (size_t)e * H * FF;
#pragma unroll
        for (int i = 0; i < 8; i++) {
            int row = r0 + 32 * i;
            const __half* s;
            if (row < 128) {
                int rA = m0 + row; if (rA >= cnt) rA = m0;
                s = g_act + (size_t)(off + rA) * FF;
            } else {
                s = W + (size_t)(n0 + row - 128) * FF;
            }
            srcp[i] = s + j * 8;
            dstoff[i] = (uint32_t)(row * ROWB + j * 16);
        }
    }

    uint32_t aoff = (uint32_t)((lane & 15) * ROWB + (lane >> 4) * 16);
    uint32_t boff = (uint32_t)((((lane >> 4) * 8 + (lane & 7)) * ROWB) + (((lane >> 3) & 1) * 16));

    float acc[4][8][4];
#pragma unroll
    for (int i = 0; i < 4; i++)
#pragma unroll
        for (int j = 0; j < 8; j++)
#pragma unroll
            for (int k = 0; k < 4; k++) acc[i][j][k] = 0.f;

    G_FILL(0, 0); CP_COMMIT();
    G_FILL(1, BK); CP_COMMIT();

    const int NIT = FF / BK;  // 16
    for (int it = 0; it < NIT; it++) {
        CP_WAIT(1);
        __syncthreads();
        int cur = it % NSTG;
        int kn = it + NSTG - 1;
        if (kn < NIT) { G_FILL(kn % NSTG, kn * BK); }
        CP_COMMIT();

        uint32_t sc = sb + cur * STG_SZ;
#pragma unroll
        for (int ks = 0; ks < 2; ks++) {
            uint32_t a[4][4];
#pragma unroll
            for (int mt = 0; mt < 4; mt++)
                ldsm4(a[mt], sc + (uint32_t)((wm * 64 + mt * 16) * ROWB + ks * 32) + aoff);
            uint32_t b[4][4];
#pragma unroll
            for (int nt16 = 0; nt16 < 4; nt16++)
                ldsm4(b[nt16], sc + BREG + (uint32_t)((wn * 64 + nt16 * 16) * ROWB + ks * 32) + boff);
#pragma unroll
            for (int mt = 0; mt < 4; mt++) {
#pragma unroll
                for (int nt = 0; nt < 8; nt++)
                    mma16(acc[mt][nt], a[mt], b[nt >> 1][(nt & 1) * 2], b[nt >> 1][(nt & 1) * 2 + 1]);
            }
        }
    }

    // weighted combine: exactly 2 contributions per token element -> atomicAdd
#pragma unroll
    for (int mt = 0; mt < 4; mt++) {
#pragma unroll
        for (int h2 = 0; h2 < 2; h2++) {
            int m = m0 + wm * 64 + mt * 16 + grp + h2 * 8;
            if (m < cnt) {
                int   r   = off + m;
                int   tok = g_perm[r];
                float p   = g_prob[r];
                float* o  = out + (size_t)tok * H;
#pragma unroll
                for (int nt = 0; nt < 8; nt++) {
                    int n = n0 + wn * 64 + nt * 8 + thr * 2;
                    atomicAdd(&o[n],     p * acc[mt][nt][h2 * 2 + 0]);
                    atomicAdd(&o[n + 1], p * acc[mt][nt][h2 * 2 + 1]);
                }
            }
        }
    }
}

// ---------------- launch ----------------
extern "C" void kernel_launch(void* const* d_in, const int* in_sizes, int n_in,
                              void* d_out, int out_size) {
    const float* x   = (const float*)d_in[0];
    const float* gw  = (const float*)d_in[1];
    const float* w13 = (const float*)d_in[2];
    const float* w2  = (const float*)d_in[3];
    float* out = (float*)d_out;

    __half* xh;   cudaGetSymbolAddress((void**)&xh,   x_h);
    __half* w13h; cudaGetSymbolAddress((void**)&w13h, w13_h);
    __half* w2h;  cudaGetSymbolAddress((void**)&w2h,  w2_h);

    cudaFuncSetAttribute(gemm1_kernel, cudaFuncAttributeMaxDynamicSharedMemorySize, SMEM_BYTES);
    cudaFuncSetAttribute(gemm2_kernel, cudaFuncAttributeMaxDynamicSharedMemorySize, SMEM_BYTES);

    prep_kernel<<<2048, 256>>>(out, (const float4*)x, (const float4*)w13,
                               (const float4*)w2, (uint2*)xh, (uint2*)w13h, (uint2*)w2h);
    router_kernel<<<(L * 32 + 255) / 256, 256>>>(x, gw);
    prefix_kernel<<<1, 32>>>();
    scatter_kernel<<<(L + 255) / 256, 256>>>();
    gemm1_kernel<<<dim3(FF / 64, ROWS / 128, NE), 128, SMEM_BYTES>>>();
    gemm2_kernel<<<dim3(H / 128, ROWS / 128, NE), 128, SMEM_BYTES>>>(out);
}